// round 15
// baseline (speedup 1.0000x reference)
#include <cuda_runtime.h>
#include <cuda_fp16.h>

typedef unsigned int u32;

#define B_    16
#define C_    8
#define H_    512
#define W_    512
#define HW_   (H_*W_)
#define NPIX  (B_*HW_)
#define PGRID 592          // 4 CTAs x 148 SMs, all co-resident (grid-sync safe)
#define NTILE (B_*H_)      // 8192 row-tiles

__device__ u32 g_cnt;
__device__ u32 g_arr;
__device__ u32 g_dep;

__device__ __forceinline__ u32 pkh(float lo, float hi) {
    __half2 h = __floats2half2_rn(lo, hi);
    return *reinterpret_cast<u32*>(&h);
}
__device__ __forceinline__ u32 pkhr(float lo, float hi) {   // relu + pack
    __half2 h = __floats2half2_rn(fmaxf(lo, 0.0f), fmaxf(hi, 0.0f));
    return *reinterpret_cast<u32*>(&h);
}

// M=pixels, N=outputs: A = activations, B = weights (persistent regs)
__device__ __forceinline__ void mma16(float* d, u32 a0, u32 a1, u32 a2, u32 a3,
                                      u32 b0, u32 b1) {
    asm volatile(
        "mma.sync.aligned.m16n8k16.row.col.f32.f16.f16.f32 "
        "{%0,%1,%2,%3},{%4,%5,%6,%7},{%8,%9},{%0,%1,%2,%3};"
        : "+f"(d[0]), "+f"(d[1]), "+f"(d[2]), "+f"(d[3])
        : "r"(a0), "r"(a1), "r"(a2), "r"(a3), "r"(b0), "r"(b1));
}

// First k-tile variant: C = {cA,cB,cA,cB} bias registers, D = accumulator.
// Removes the per-chunk accumulator-init MOVs; arithmetic identical.
__device__ __forceinline__ void mma16_bias(float* d, u32 a0, u32 a1, u32 a2, u32 a3,
                                           u32 b0, u32 b1, float cA, float cB) {
    asm volatile(
        "mma.sync.aligned.m16n8k16.row.col.f32.f16.f16.f32 "
        "{%0,%1,%2,%3},{%4,%5,%6,%7},{%8,%9},{%10,%11,%10,%11};"
        : "=f"(d[0]), "=f"(d[1]), "=f"(d[2]), "=f"(d[3])
        : "r"(a0), "r"(a1), "r"(a2), "r"(a3), "r"(b0), "r"(b1),
          "f"(cA), "f"(cB));
}

__device__ __forceinline__ int swz(int px, int w) {
    return px * 20 + (w ^ ((px >> 3) & 15));
}

__device__ __forceinline__ void loadrow(const float* p, bool okRow, bool okL, bool okR,
                                        int lane, float4& v, float& l, float& r) {
    v = okRow ? __ldg(reinterpret_cast<const float4*>(p)) : make_float4(0.f, 0.f, 0.f, 0.f);
    l = __shfl_up_sync(0xffffffffu, v.w, 1);
    r = __shfl_down_sync(0xffffffffu, v.x, 1);
    if (lane == 0)  l = (okRow && okL) ? __ldg(p - 1) : 0.0f;
    if (lane == 31) r = (okRow && okR) ? __ldg(p + 4) : 0.0f;
}

__global__ void __launch_bounds__(128, 4)
k_main(const float* __restrict__ x,
       const float* __restrict__ w1, const float* __restrict__ b1,
       const float* __restrict__ w2, const float* __restrict__ b2,
       const float* __restrict__ w3, const float* __restrict__ b3,
       const float* __restrict__ growth,
       float* __restrict__ out)
{
    __shared__ __align__(16) u32 sbuf[4 * 128 * 20];   // 40 KB
    __shared__ u32 s_part;
    __shared__ float s_bbase;

    const int tid  = threadIdx.x;
    const int wid  = tid >> 5;
    const int lane = tid & 31;
    const int q = lane >> 2;
    const int r = lane & 3;
    u32* bw = sbuf + wid * (128 * 20);

    // ================= Phase A: global alive count =================
    if (tid == 0) s_part = 0u;
    __syncthreads();
    {
        u32 cnt = 0;
        for (int b = 0; b < B_; b++) {
            const float4* p = reinterpret_cast<const float4*>(
                x + (size_t)b * (C_ * HW_) + (size_t)3 * HW_);
            for (int i = blockIdx.x * 128 + tid; i < HW_ / 4; i += PGRID * 128) {
                float4 v = __ldg(p + i);
                cnt += (v.x > 0.1f) + (v.y > 0.1f) + (v.z > 0.1f) + (v.w > 0.1f);
            }
        }
        #pragma unroll
        for (int o = 16; o; o >>= 1) cnt += __shfl_down_sync(0xffffffffu, cnt, o);
        if (lane == 0) atomicAdd(&s_part, cnt);
    }
    __syncthreads();
    if (tid == 0) {
        atomicAdd(&g_cnt, s_part);
        __threadfence();
        atomicAdd(&g_arr, 1u);
    }
    {
        volatile u32* va = &g_arr;
        while (*va < PGRID) __nanosleep(128);
    }
    __threadfence();
    if (tid == 0) {
        u32 total = *((volatile u32*)&g_cnt);
        s_bbase = ((float)total < 0.2f * (float)NPIX) ? 0.2f : 0.0f;
    }
    __syncthreads();
    const float bbase = s_bbase;
    if (tid == 0) {
        u32 d = atomicAdd(&g_dep, 1u);
        if (d == PGRID - 1) {
            g_cnt = 0u; g_arr = 0u; g_dep = 0u;
            __threadfence();
        }
    }

    // ================= persistent weight fragments =================
    u32 W1f[4][2][2];
    #pragma unroll
    for (int nt = 0; nt < 4; nt++)
        #pragma unroll
        for (int kt = 0; kt < 2; kt++) {
            const float* wr = w1 + (8 * nt + q) * 24;
            int k0 = 16 * kt + 2 * r;
            W1f[nt][kt][0] = pkh(__ldg(&wr[k0]), __ldg(&wr[k0 + 1]));
            W1f[nt][kt][1] = (kt == 0)
                ? pkh(__ldg(&wr[k0 + 8]), __ldg(&wr[k0 + 9])) : 0u;
        }
    u32 W2f[4][2][2];
    #pragma unroll
    for (int nt = 0; nt < 4; nt++)
        #pragma unroll
        for (int kt = 0; kt < 2; kt++) {
            const float* wr = w2 + (8 * nt + q) * 32;
            int k0 = 16 * kt + 2 * r;
            W2f[nt][kt][0] = pkh(__ldg(&wr[k0]), __ldg(&wr[k0 + 1]));
            W2f[nt][kt][1] = pkh(__ldg(&wr[k0 + 8]), __ldg(&wr[k0 + 9]));
        }
    u32 W3f[2][2];
    #pragma unroll
    for (int kt = 0; kt < 2; kt++) {
        const float* wr = w3 + q * 32;
        int k0 = 16 * kt + 2 * r;
        W3f[kt][0] = pkh(__ldg(&wr[k0]), __ldg(&wr[k0 + 1]));
        W3f[kt][1] = pkh(__ldg(&wr[k0 + 8]), __ldg(&wr[k0 + 9]));
    }
    float bA1[4], bB1[4], bA2[4], bB2[4];
    #pragma unroll
    for (int nt = 0; nt < 4; nt++) {
        bA1[nt] = __ldg(&b1[8 * nt + 2 * r]); bB1[nt] = __ldg(&b1[8 * nt + 2 * r + 1]);
        bA2[nt] = __ldg(&b2[8 * nt + 2 * r]); bB2[nt] = __ldg(&b2[8 * nt + 2 * r + 1]);
    }
    const float bA3 = __ldg(&b3[2 * r]), bB3 = __ldg(&b3[2 * r + 1]);
    const float gr  = __ldg(&growth[0]);
    const float AT  = 0.1f;

    // lane word-bases for strength-reduced fragment addressing
    u32 lbw[4];
    #pragma unroll
    for (int j = 0; j < 4; j++) lbw[j] = q * 20 + (r ^ j);

    // k-pad words 12..15 stay zero (fragment loads land in words [0,16) only)
    #pragma unroll
    for (int i = 0; i < 4; i++) {
        int px = 4 * lane + i;
        bw[swz(px, 12)] = 0u; bw[swz(px, 13)] = 0u;
        bw[swz(px, 14)] = 0u; bw[swz(px, 15)] = 0u;
    }

    // ================= Phase B: persistent tile loop =================
    for (int t = blockIdx.x; t < NTILE; t += PGRID) {
        const int yy = t & (H_ - 1);
        const int bz = t >> 9;
        const int x0 = wid * 128;
        const float* xb = x + (size_t)bz * (C_ * HW_);

        const bool okT = (yy > 0), okB = (yy < H_ - 1);
        const bool okL = (x0 > 0), okR = (x0 + 128 < W_);

        __syncwarp();   // prior tile fully consumed before overwriting pbuf

        // ---- perceive ----
        u32 bm0 = 0, bm1 = 0, bm2 = 0, bm3 = 0;
        #pragma unroll
        for (int p = 0; p < 4; p++) {
            float m0v[4], sx0[4], sy0[4];
            float m1v[4], sx1[4], sy1[4];
            bool alive_px[4] = {false, false, false, false};
            #pragma unroll
            for (int sub = 0; sub < 2; sub++) {
                const int ch = 2 * p + sub;
                const float* base = xb + (size_t)ch * HW_ + (size_t)yy * W_ + x0 + 4 * lane;
                float4 tt, mm, bb; float tl, tr, ml, mr, bl, br;
                loadrow(base - W_, okT,  okL, okR, lane, tt, tl, tr);
                loadrow(base,      true, okL, okR, lane, mm, ml, mr);
                loadrow(base + W_, okB,  okL, okR, lane, bb, bl, br);

                float nt_[6] = {tl, tt.x, tt.y, tt.z, tt.w, tr};
                float nm_[6] = {ml, mm.x, mm.y, mm.z, mm.w, mr};
                float nb_[6] = {bl, bb.x, bb.y, bb.z, bb.w, br};

                float* mv = sub ? m1v : m0v;
                float* sx = sub ? sx1 : sx0;
                float* sy = sub ? sy1 : sy0;
                #pragma unroll
                for (int i = 0; i < 4; i++) {
                    mv[i] = nm_[i + 1];
                    sx[i] = (nt_[i + 2] - nt_[i]) + 2.0f * (nm_[i + 2] - nm_[i])
                          + (nb_[i + 2] - nb_[i]);
                    sy[i] = (nb_[i] + 2.0f * nb_[i + 1] + nb_[i + 2])
                          - (nt_[i] + 2.0f * nt_[i + 1] + nt_[i + 2]);
                }
                if (p == 1 && sub == 1) {
                    bool a[6];
                    #pragma unroll
                    for (int j = 0; j < 6; j++)
                        a[j] = (nt_[j] > AT) | (nm_[j] > AT) | (nb_[j] > AT);
                    #pragma unroll
                    for (int i = 0; i < 4; i++)
                        alive_px[i] = a[i] | a[i + 1] | a[i + 2];
                }
            }
            #pragma unroll
            for (int i = 0; i < 4; i++) {
                int px = 4 * lane + i;
                bw[swz(px, p)]     = pkh(m0v[i], m1v[i]);
                bw[swz(px, 4 + p)] = pkh(sx0[i], sx1[i]);
                bw[swz(px, 8 + p)] = pkh(sy0[i], sy1[i]);
            }
            if (p == 1) {
                bm0 = __ballot_sync(0xffffffffu, alive_px[0]);
                bm1 = __ballot_sync(0xffffffffu, alive_px[1]);
                bm2 = __ballot_sync(0xffffffffu, alive_px[2]);
                bm3 = __ballot_sync(0xffffffffu, alive_px[3]);
            }
        }
        __syncwarp();

        // ---- L2 prefetch of NEXT tile's input rows (overlaps GEMM below) ----
        {
            int tn = t + PGRID;
            if (tn < NTILE) {
                int yyn = tn & (H_ - 1);
                int bzn = tn >> 9;
                const float* xbn = x + (size_t)bzn * (C_ * HW_);
                #pragma unroll
                for (int pl = 0; pl < 3; pl++) {
                    int l   = lane + 32 * pl;        // 0..95
                    int ch  = l / 12;
                    int rem = l - ch * 12;
                    int dy  = (rem >> 2) - 1;
                    int seg = rem & 3;
                    int yr  = yyn + dy;
                    if (yr >= 0 && yr < H_) {
                        const float* pa = xbn + (size_t)ch * HW_
                                        + (size_t)yr * W_ + x0 + seg * 32;
                        asm volatile("prefetch.global.L2 [%0];" :: "l"(pa));
                    }
                }
            }
        }

        // ---- 4 chunks of 32 px; layers chained in registers; dx staged fp16 ----
        #pragma unroll
        for (int cidx = 0; cidx < 4; cidx++) {
            const int P = 32 * cidx;

            // Layer 1: kt=0 seeds accumulators with bias via MMA C-operand
            float d1[2][4][4];
            #pragma unroll
            for (int kt = 0; kt < 2; kt++)
                #pragma unroll
                for (int mt = 0; mt < 2; mt++) {
                    const int m  = (4 * cidx + 2 * mt) & 15;
                    const int m1 = (m + 1) & 15;
                    const int C0 = (P + 16 * mt) * 20
                                 + ((8 * kt) ^ (m  & 8)) + (m  & 4);
                    const int C1 = (P + 16 * mt + 8) * 20
                                 + ((8 * kt) ^ (m1 & 8)) + (m1 & 4);
                    const int C2 = (P + 16 * mt) * 20
                                 + ((8 * kt) ^ (m  & 8)) + (4 ^ (m  & 4));
                    const int C3 = (P + 16 * mt + 8) * 20
                                 + ((8 * kt) ^ (m1 & 8)) + (4 ^ (m1 & 4));
                    u32 a0 = bw[lbw[m  & 3] + C0];
                    u32 a1 = bw[lbw[m1 & 3] + C1];
                    u32 a2 = bw[lbw[m  & 3] + C2];
                    u32 a3 = bw[lbw[m1 & 3] + C3];
                    #pragma unroll
                    for (int nt = 0; nt < 4; nt++) {
                        if (kt == 0)
                            mma16_bias(d1[mt][nt], a0, a1, a2, a3,
                                       W1f[nt][0][0], W1f[nt][0][1], bA1[nt], bB1[nt]);
                        else
                            mma16(d1[mt][nt], a0, a1, a2, a3,
                                  W1f[nt][1][0], W1f[nt][1][1]);
                    }
                }

            // Layer 2: in-register relu+pack; kt=0 seeds with bias
            float d2[2][4][4];
            #pragma unroll
            for (int mt = 0; mt < 2; mt++)
                #pragma unroll
                for (int kt = 0; kt < 2; kt++) {
                    u32 a0 = pkhr(d1[mt][2 * kt][0],     d1[mt][2 * kt][1]);
                    u32 a1 = pkhr(d1[mt][2 * kt][2],     d1[mt][2 * kt][3]);
                    u32 a2 = pkhr(d1[mt][2 * kt + 1][0], d1[mt][2 * kt + 1][1]);
                    u32 a3 = pkhr(d1[mt][2 * kt + 1][2], d1[mt][2 * kt + 1][3]);
                    #pragma unroll
                    for (int nt = 0; nt < 4; nt++) {
                        if (kt == 0)
                            mma16_bias(d2[mt][nt], a0, a1, a2, a3,
                                       W2f[nt][0][0], W2f[nt][0][1], bA2[nt], bB2[nt]);
                        else
                            mma16(d2[mt][nt], a0, a1, a2, a3,
                                  W2f[nt][1][0], W2f[nt][1][1]);
                    }
                }

            // Layer 3: kt=0 seeds with bias
            float e[2][4];
            #pragma unroll
            for (int mt = 0; mt < 2; mt++)
                #pragma unroll
                for (int kt = 0; kt < 2; kt++) {
                    u32 a0 = pkhr(d2[mt][2 * kt][0],     d2[mt][2 * kt][1]);
                    u32 a1 = pkhr(d2[mt][2 * kt][2],     d2[mt][2 * kt][3]);
                    u32 a2 = pkhr(d2[mt][2 * kt + 1][0], d2[mt][2 * kt + 1][1]);
                    u32 a3 = pkhr(d2[mt][2 * kt + 1][2], d2[mt][2 * kt + 1][3]);
                    if (kt == 0)
                        mma16_bias(e[mt], a0, a1, a2, a3,
                                   W3f[0][0], W3f[0][1], bA3, bB3);
                    else
                        mma16(e[mt], a0, a1, a2, a3, W3f[1][0], W3f[1][1]);
                }

            // stage raw dx (pre-scale) as fp16 pairs into spare words 16..19
            #pragma unroll
            for (int mt = 0; mt < 2; mt++)
                #pragma unroll
                for (int h = 0; h < 2; h++) {
                    int px = P + 16 * mt + 8 * h + q;
                    int s  = ((px >> 2) ^ (2 * (px & 3))) | ((px & 3) << 5);
                    bw[s * 20 + 16 + r] = pkh(e[mt][2 * h], e[mt][2 * h + 1]);
                }
        }
        __syncwarp();   // dx staging visible across lanes

        // ---- vectorized epilogue: 4 px/lane, all 8 channels ----
        {
            const float* xrow = xb + (size_t)yy * W_ + x0 + 4 * lane;
            float* orow = out + (size_t)bz * (C_ * HW_) + (size_t)yy * W_ + x0 + 4 * lane;

            u32 dxw[4][4];
            #pragma unroll
            for (int i = 0; i < 4; i++) {
                int s = (lane ^ (2 * i)) | (i << 5);
                uint4 v = *reinterpret_cast<const uint4*>(&bw[s * 20 + 16]);
                dxw[i][0] = v.x; dxw[i][1] = v.y; dxw[i][2] = v.z; dxw[i][3] = v.w;
            }
            u32 bms[4] = {bm0, bm1, bm2, bm3};

            #pragma unroll
            for (int j = 0; j < 4; j++) {        // channel pair (2j, 2j+1)
                float4 xa = __ldg(reinterpret_cast<const float4*>(
                    xrow + (size_t)(2 * j) * HW_));
                float4 xc = __ldg(reinterpret_cast<const float4*>(
                    xrow + (size_t)(2 * j + 1) * HW_));
                float oa[4], oc[4];
                const float* xaf = &xa.x;
                const float* xcf = &xc.x;
                #pragma unroll
                for (int i = 0; i < 4; i++) {
                    __half2 hv = *reinterpret_cast<__half2*>(&dxw[i][j]);
                    float2 f = __half22float2(hv);
                    float dx0 = f.x * gr;
                    float dx1 = f.y * gr;
                    if (j == 1) {                // ch3 boost
                        if ((bms[i] >> lane) & 1u) dx1 += bbase;
                    }
                    float n0 = fminf(fmaxf(xaf[i] + dx0, -1.0f), 1.0f);
                    float n1 = fminf(fmaxf(xcf[i] + dx1, -1.0f), 1.0f);
                    if (j == 1) n1 = fmaxf(n1, 0.0f);   // alpha clamp
                    oa[i] = n0; oc[i] = n1;
                }
                *reinterpret_cast<float4*>(orow + (size_t)(2 * j) * HW_)
                    = make_float4(oa[0], oa[1], oa[2], oa[3]);
                *reinterpret_cast<float4*>(orow + (size_t)(2 * j + 1) * HW_)
                    = make_float4(oc[0], oc[1], oc[2], oc[3]);
            }
        }
    }
}

extern "C" void kernel_launch(void* const* d_in, const int* in_sizes, int n_in,
                              void* d_out, int out_size)
{
    const float* x  = (const float*)d_in[0];
    const float* w1 = (const float*)d_in[1];
    const float* b1 = (const float*)d_in[2];
    const float* w2 = (const float*)d_in[3];
    const float* b2 = (const float*)d_in[4];
    const float* w3 = (const float*)d_in[5];
    const float* b3 = (const float*)d_in[6];
    const float* gr = (const float*)d_in[7];
    float* out = (float*)d_out;

    k_main<<<PGRID, 128>>>(x, w1, b1, w2, b2, w3, b3, gr, out);
}

// round 16
// speedup vs baseline: 1.4168x; 1.4168x over previous
#include <cuda_runtime.h>
#include <cuda_fp16.h>

typedef unsigned int u32;

#define B_    16
#define C_    8
#define H_    512
#define W_    512
#define HW_   (H_*W_)
#define NPIX  (B_*HW_)
#define PGRID 592          // 4 CTAs x 148 SMs, all co-resident (grid-sync safe)
#define NTILE (B_*H_)      // 8192 row-tiles

__device__ u32 g_cnt;
__device__ u32 g_arr;
__device__ u32 g_dep;

__device__ __forceinline__ u32 pkh(float lo, float hi) {
    __half2 h = __floats2half2_rn(lo, hi);
    return *reinterpret_cast<u32*>(&h);
}
__device__ __forceinline__ u32 pkhr(float lo, float hi) {   // relu + pack
    __half2 h = __floats2half2_rn(fmaxf(lo, 0.0f), fmaxf(hi, 0.0f));
    return *reinterpret_cast<u32*>(&h);
}

// M=pixels, N=outputs: A = activations, B = weights (persistent regs)
__device__ __forceinline__ void mma16(float* d, u32 a0, u32 a1, u32 a2, u32 a3,
                                      u32 b0, u32 b1) {
    asm volatile(
        "mma.sync.aligned.m16n8k16.row.col.f32.f16.f16.f32 "
        "{%0,%1,%2,%3},{%4,%5,%6,%7},{%8,%9},{%0,%1,%2,%3};"
        : "+f"(d[0]), "+f"(d[1]), "+f"(d[2]), "+f"(d[3])
        : "r"(a0), "r"(a1), "r"(a2), "r"(a3), "r"(b0), "r"(b1));
}

__device__ __forceinline__ int swz(int px, int w) {
    return px * 20 + (w ^ ((px >> 3) & 15));
}

// raw row preload: vector + edge scalar (lane 0: left halo, lane 31: right halo)
__device__ __forceinline__ void prerow(const float* p, bool okRow, bool okL, bool okR,
                                       int lane, float4& v, float& e) {
    v = okRow ? __ldg(reinterpret_cast<const float4*>(p))
              : make_float4(0.f, 0.f, 0.f, 0.f);
    e = 0.0f;
    if (lane == 0  && okRow && okL) e = __ldg(p - 1);
    if (lane == 31 && okRow && okR) e = __ldg(p + 4);
}

// consume-time halo expansion via shuffles
__device__ __forceinline__ void expand(const float4& v, float e, int lane, float* n) {
    float l = __shfl_up_sync(0xffffffffu, v.w, 1);
    float r = __shfl_down_sync(0xffffffffu, v.x, 1);
    if (lane == 0)  l = e;
    if (lane == 31) r = e;
    n[0] = l; n[1] = v.x; n[2] = v.y; n[3] = v.z; n[4] = v.w; n[5] = r;
}

__global__ void __launch_bounds__(128, 4)
k_main(const float* __restrict__ x,
       const float* __restrict__ w1, const float* __restrict__ b1,
       const float* __restrict__ w2, const float* __restrict__ b2,
       const float* __restrict__ w3, const float* __restrict__ b3,
       const float* __restrict__ growth,
       float* __restrict__ out)
{
    __shared__ __align__(16) u32 sbuf[4 * 128 * 20];   // 40 KB
    __shared__ u32 s_part;
    __shared__ float s_bbase;

    const int tid  = threadIdx.x;
    const int wid  = tid >> 5;
    const int lane = tid & 31;
    const int q = lane >> 2;
    const int r = lane & 3;
    u32* bw = sbuf + wid * (128 * 20);

    // ================= Phase A: global alive count =================
    if (tid == 0) s_part = 0u;
    __syncthreads();
    {
        u32 cnt = 0;
        for (int b = 0; b < B_; b++) {
            const float4* p = reinterpret_cast<const float4*>(
                x + (size_t)b * (C_ * HW_) + (size_t)3 * HW_);
            for (int i = blockIdx.x * 128 + tid; i < HW_ / 4; i += PGRID * 128) {
                float4 v = __ldg(p + i);
                cnt += (v.x > 0.1f) + (v.y > 0.1f) + (v.z > 0.1f) + (v.w > 0.1f);
            }
        }
        #pragma unroll
        for (int o = 16; o; o >>= 1) cnt += __shfl_down_sync(0xffffffffu, cnt, o);
        if (lane == 0) atomicAdd(&s_part, cnt);
    }
    __syncthreads();
    if (tid == 0) {
        atomicAdd(&g_cnt, s_part);
        __threadfence();
        atomicAdd(&g_arr, 1u);
    }
    {
        volatile u32* va = &g_arr;
        while (*va < PGRID) __nanosleep(128);
    }
    __threadfence();
    if (tid == 0) {
        u32 total = *((volatile u32*)&g_cnt);
        s_bbase = ((float)total < 0.2f * (float)NPIX) ? 0.2f : 0.0f;
    }
    __syncthreads();
    const float bbase = s_bbase;
    if (tid == 0) {
        u32 d = atomicAdd(&g_dep, 1u);
        if (d == PGRID - 1) {
            g_cnt = 0u; g_arr = 0u; g_dep = 0u;
            __threadfence();
        }
    }

    // ================= persistent weight fragments =================
    u32 W1f[4][2][2];
    #pragma unroll
    for (int nt = 0; nt < 4; nt++)
        #pragma unroll
        for (int kt = 0; kt < 2; kt++) {
            const float* wr = w1 + (8 * nt + q) * 24;
            int k0 = 16 * kt + 2 * r;
            W1f[nt][kt][0] = pkh(__ldg(&wr[k0]), __ldg(&wr[k0 + 1]));
            W1f[nt][kt][1] = (kt == 0)
                ? pkh(__ldg(&wr[k0 + 8]), __ldg(&wr[k0 + 9])) : 0u;
        }
    u32 W2f[4][2][2];
    #pragma unroll
    for (int nt = 0; nt < 4; nt++)
        #pragma unroll
        for (int kt = 0; kt < 2; kt++) {
            const float* wr = w2 + (8 * nt + q) * 32;
            int k0 = 16 * kt + 2 * r;
            W2f[nt][kt][0] = pkh(__ldg(&wr[k0]), __ldg(&wr[k0 + 1]));
            W2f[nt][kt][1] = pkh(__ldg(&wr[k0 + 8]), __ldg(&wr[k0 + 9]));
        }
    u32 W3f[2][2];
    #pragma unroll
    for (int kt = 0; kt < 2; kt++) {
        const float* wr = w3 + q * 32;
        int k0 = 16 * kt + 2 * r;
        W3f[kt][0] = pkh(__ldg(&wr[k0]), __ldg(&wr[k0 + 1]));
        W3f[kt][1] = pkh(__ldg(&wr[k0 + 8]), __ldg(&wr[k0 + 9]));
    }
    float bA1[4], bB1[4], bA2[4], bB2[4];
    #pragma unroll
    for (int nt = 0; nt < 4; nt++) {
        bA1[nt] = __ldg(&b1[8 * nt + 2 * r]); bB1[nt] = __ldg(&b1[8 * nt + 2 * r + 1]);
        bA2[nt] = __ldg(&b2[8 * nt + 2 * r]); bB2[nt] = __ldg(&b2[8 * nt + 2 * r + 1]);
    }
    const float bA3 = __ldg(&b3[2 * r]), bB3 = __ldg(&b3[2 * r + 1]);
    const float gr  = __ldg(&growth[0]);
    const float AT  = 0.1f;

    // lane word-bases for strength-reduced fragment addressing
    u32 lbw[4];
    #pragma unroll
    for (int j = 0; j < 4; j++) lbw[j] = q * 20 + (r ^ j);

    // k-pad words 12..15 stay zero (fragment loads land in words [0,16) only)
    #pragma unroll
    for (int i = 0; i < 4; i++) {
        int px = 4 * lane + i;
        bw[swz(px, 12)] = 0u; bw[swz(px, 13)] = 0u;
        bw[swz(px, 14)] = 0u; bw[swz(px, 15)] = 0u;
    }

    // ================= Phase B: persistent tile loop =================
    for (int t = blockIdx.x; t < NTILE; t += PGRID) {
        const int yy = t & (H_ - 1);
        const int bz = t >> 9;
        const int x0 = wid * 128;
        const float* xb = x + (size_t)bz * (C_ * HW_);

        const bool okT = (yy > 0), okB = (yy < H_ - 1);
        const bool okL = (x0 > 0), okR = (x0 + 128 < W_);

        __syncwarp();   // prior tile fully consumed before overwriting pbuf

        // ---- perceive: 8 channels, 1-deep software pipeline on row loads ----
        u32 bm0 = 0, bm1 = 0, bm2 = 0, bm3 = 0;
        float m0v[4], sx0[4], sy0[4];          // even-channel results awaiting pairing

        float4 cT, cM, cB; float eT, eM, eB;   // current channel rows
        {
            const float* b0 = xb + (size_t)yy * W_ + x0 + 4 * lane;   // ch 0
            prerow(b0 - W_, okT,  okL, okR, lane, cT, eT);
            prerow(b0,      true, okL, okR, lane, cM, eM);
            prerow(b0 + W_, okB,  okL, okR, lane, cB, eB);
        }

        #pragma unroll
        for (int s = 0; s < 8; s++) {
            // issue next channel's loads BEFORE consuming current (latency overlap)
            float4 nT, nM, nB; float fT = 0.f, fM = 0.f, fB = 0.f;
            if (s < 7) {
                const float* bn = xb + (size_t)(s + 1) * HW_
                                + (size_t)yy * W_ + x0 + 4 * lane;
                prerow(bn - W_, okT,  okL, okR, lane, nT, fT);
                prerow(bn,      true, okL, okR, lane, nM, fM);
                prerow(bn + W_, okB,  okL, okR, lane, nB, fB);
            } else {
                nT = nM = nB = make_float4(0.f, 0.f, 0.f, 0.f);
            }

            // consume current channel
            float nt_[6], nm_[6], nb_[6];
            expand(cT, eT, lane, nt_);
            expand(cM, eM, lane, nm_);
            expand(cB, eB, lane, nb_);

            float mv[4], sx[4], sy[4];
            #pragma unroll
            for (int i = 0; i < 4; i++) {
                mv[i] = nm_[i + 1];
                sx[i] = (nt_[i + 2] - nt_[i]) + 2.0f * (nm_[i + 2] - nm_[i])
                      + (nb_[i + 2] - nb_[i]);
                sy[i] = (nb_[i] + 2.0f * nb_[i + 1] + nb_[i + 2])
                      - (nt_[i] + 2.0f * nt_[i + 1] + nt_[i + 2]);
            }

            if (s == 3) {   // channel 3: 3x3 any-alive -> ballots
                bool a[6];
                #pragma unroll
                for (int j = 0; j < 6; j++)
                    a[j] = (nt_[j] > AT) | (nm_[j] > AT) | (nb_[j] > AT);
                bm0 = __ballot_sync(0xffffffffu, a[0] | a[1] | a[2]);
                bm1 = __ballot_sync(0xffffffffu, a[1] | a[2] | a[3]);
                bm2 = __ballot_sync(0xffffffffu, a[2] | a[3] | a[4]);
                bm3 = __ballot_sync(0xffffffffu, a[3] | a[4] | a[5]);
            }

            if ((s & 1) == 0) {
                #pragma unroll
                for (int i = 0; i < 4; i++) {
                    m0v[i] = mv[i]; sx0[i] = sx[i]; sy0[i] = sy[i];
                }
            } else {
                const int p = s >> 1;
                #pragma unroll
                for (int i = 0; i < 4; i++) {
                    int px = 4 * lane + i;
                    bw[swz(px, p)]     = pkh(m0v[i], mv[i]);
                    bw[swz(px, 4 + p)] = pkh(sx0[i], sx[i]);
                    bw[swz(px, 8 + p)] = pkh(sy0[i], sy[i]);
                }
            }

            cT = nT; cM = nM; cB = nB; eT = fT; eM = fM; eB = fB;
        }
        __syncwarp();

        // ---- L2 prefetch of NEXT tile's input rows (overlaps GEMM below) ----
        {
            int tn = t + PGRID;
            if (tn < NTILE) {
                int yyn = tn & (H_ - 1);
                int bzn = tn >> 9;
                const float* xbn = x + (size_t)bzn * (C_ * HW_);
                #pragma unroll
                for (int pl = 0; pl < 3; pl++) {
                    int l   = lane + 32 * pl;        // 0..95
                    int ch  = l / 12;
                    int rem = l - ch * 12;
                    int dy  = (rem >> 2) - 1;
                    int seg = rem & 3;
                    int yr  = yyn + dy;
                    if (yr >= 0 && yr < H_) {
                        const float* pa = xbn + (size_t)ch * HW_
                                        + (size_t)yr * W_ + x0 + seg * 32;
                        asm volatile("prefetch.global.L2 [%0];" :: "l"(pa));
                    }
                }
            }
        }

        // ---- 4 chunks of 32 px; layers chained in registers; dx staged fp16 ----
        #pragma unroll
        for (int cidx = 0; cidx < 4; cidx++) {
            const int P = 32 * cidx;

            float d1[2][4][4];
            #pragma unroll
            for (int mt = 0; mt < 2; mt++)
                #pragma unroll
                for (int nt = 0; nt < 4; nt++) {
                    d1[mt][nt][0] = bA1[nt]; d1[mt][nt][1] = bB1[nt];
                    d1[mt][nt][2] = bA1[nt]; d1[mt][nt][3] = bB1[nt];
                }
            #pragma unroll
            for (int kt = 0; kt < 2; kt++)
                #pragma unroll
                for (int mt = 0; mt < 2; mt++) {
                    const int m  = (4 * cidx + 2 * mt) & 15;
                    const int m1 = (m + 1) & 15;
                    const int C0 = (P + 16 * mt) * 20
                                 + ((8 * kt) ^ (m  & 8)) + (m  & 4);
                    const int C1 = (P + 16 * mt + 8) * 20
                                 + ((8 * kt) ^ (m1 & 8)) + (m1 & 4);
                    const int C2 = (P + 16 * mt) * 20
                                 + ((8 * kt) ^ (m  & 8)) + (4 ^ (m  & 4));
                    const int C3 = (P + 16 * mt + 8) * 20
                                 + ((8 * kt) ^ (m1 & 8)) + (4 ^ (m1 & 4));
                    u32 a0 = bw[lbw[m  & 3] + C0];
                    u32 a1 = bw[lbw[m1 & 3] + C1];
                    u32 a2 = bw[lbw[m  & 3] + C2];
                    u32 a3 = bw[lbw[m1 & 3] + C3];
                    #pragma unroll
                    for (int nt = 0; nt < 4; nt++)
                        mma16(d1[mt][nt], a0, a1, a2, a3, W1f[nt][kt][0], W1f[nt][kt][1]);
                }

            float d2[2][4][4];
            #pragma unroll
            for (int mt = 0; mt < 2; mt++)
                #pragma unroll
                for (int nt = 0; nt < 4; nt++) {
                    d2[mt][nt][0] = bA2[nt]; d2[mt][nt][1] = bB2[nt];
                    d2[mt][nt][2] = bA2[nt]; d2[mt][nt][3] = bB2[nt];
                }
            #pragma unroll
            for (int mt = 0; mt < 2; mt++)
                #pragma unroll
                for (int kt = 0; kt < 2; kt++) {
                    u32 a0 = pkhr(d1[mt][2 * kt][0],     d1[mt][2 * kt][1]);
                    u32 a1 = pkhr(d1[mt][2 * kt][2],     d1[mt][2 * kt][3]);
                    u32 a2 = pkhr(d1[mt][2 * kt + 1][0], d1[mt][2 * kt + 1][1]);
                    u32 a3 = pkhr(d1[mt][2 * kt + 1][2], d1[mt][2 * kt + 1][3]);
                    #pragma unroll
                    for (int nt = 0; nt < 4; nt++)
                        mma16(d2[mt][nt], a0, a1, a2, a3, W2f[nt][kt][0], W2f[nt][kt][1]);
                }

            float e[2][4];
            #pragma unroll
            for (int mt = 0; mt < 2; mt++) {
                e[mt][0] = bA3; e[mt][1] = bB3; e[mt][2] = bA3; e[mt][3] = bB3;
            }
            #pragma unroll
            for (int mt = 0; mt < 2; mt++)
                #pragma unroll
                for (int kt = 0; kt < 2; kt++) {
                    u32 a0 = pkhr(d2[mt][2 * kt][0],     d2[mt][2 * kt][1]);
                    u32 a1 = pkhr(d2[mt][2 * kt][2],     d2[mt][2 * kt][3]);
                    u32 a2 = pkhr(d2[mt][2 * kt + 1][0], d2[mt][2 * kt + 1][1]);
                    u32 a3 = pkhr(d2[mt][2 * kt + 1][2], d2[mt][2 * kt + 1][3]);
                    mma16(e[mt], a0, a1, a2, a3, W3f[kt][0], W3f[kt][1]);
                }

            // stage raw dx (pre-scale) as fp16 pairs into spare words 16..19
            #pragma unroll
            for (int mt = 0; mt < 2; mt++)
                #pragma unroll
                for (int h = 0; h < 2; h++) {
                    int px = P + 16 * mt + 8 * h + q;
                    int s  = ((px >> 2) ^ (2 * (px & 3))) | ((px & 3) << 5);
                    bw[s * 20 + 16 + r] = pkh(e[mt][2 * h], e[mt][2 * h + 1]);
                }
        }
        __syncwarp();   // dx staging visible across lanes

        // ---- vectorized epilogue: 4 px/lane, all 8 channels ----
        {
            const float* xrow = xb + (size_t)yy * W_ + x0 + 4 * lane;
            float* orow = out + (size_t)bz * (C_ * HW_) + (size_t)yy * W_ + x0 + 4 * lane;

            u32 dxw[4][4];
            #pragma unroll
            for (int i = 0; i < 4; i++) {
                int s = (lane ^ (2 * i)) | (i << 5);
                uint4 v = *reinterpret_cast<const uint4*>(&bw[s * 20 + 16]);
                dxw[i][0] = v.x; dxw[i][1] = v.y; dxw[i][2] = v.z; dxw[i][3] = v.w;
            }
            u32 bms[4] = {bm0, bm1, bm2, bm3};

            #pragma unroll
            for (int j = 0; j < 4; j++) {        // channel pair (2j, 2j+1)
                float4 xa = __ldg(reinterpret_cast<const float4*>(
                    xrow + (size_t)(2 * j) * HW_));
                float4 xc = __ldg(reinterpret_cast<const float4*>(
                    xrow + (size_t)(2 * j + 1) * HW_));
                float oa[4], oc[4];
                const float* xaf = &xa.x;
                const float* xcf = &xc.x;
                #pragma unroll
                for (int i = 0; i < 4; i++) {
                    __half2 hv = *reinterpret_cast<__half2*>(&dxw[i][j]);
                    float2 f = __half22float2(hv);
                    float dx0 = f.x * gr;
                    float dx1 = f.y * gr;
                    if (j == 1) {                // ch3 boost
                        if ((bms[i] >> lane) & 1u) dx1 += bbase;
                    }
                    float n0 = fminf(fmaxf(xaf[i] + dx0, -1.0f), 1.0f);
                    float n1 = fminf(fmaxf(xcf[i] + dx1, -1.0f), 1.0f);
                    if (j == 1) n1 = fmaxf(n1, 0.0f);   // alpha clamp
                    oa[i] = n0; oc[i] = n1;
                }
                *reinterpret_cast<float4*>(orow + (size_t)(2 * j) * HW_)
                    = make_float4(oa[0], oa[1], oa[2], oa[3]);
                *reinterpret_cast<float4*>(orow + (size_t)(2 * j + 1) * HW_)
                    = make_float4(oc[0], oc[1], oc[2], oc[3]);
            }
        }
    }
}

extern "C" void kernel_launch(void* const* d_in, const int* in_sizes, int n_in,
                              void* d_out, int out_size)
{
    const float* x  = (const float*)d_in[0];
    const float* w1 = (const float*)d_in[1];
    const float* b1 = (const float*)d_in[2];
    const float* w2 = (const float*)d_in[3];
    const float* b2 = (const float*)d_in[4];
    const float* w3 = (const float*)d_in[5];
    const float* b3 = (const float*)d_in[6];
    const float* gr = (const float*)d_in[7];
    float* out = (float*)d_out;

    k_main<<<PGRID, 128>>>(x, w1, b1, w2, b2, w3, b3, gr, out);
}

// round 17
// speedup vs baseline: 1.4433x; 1.0187x over previous
#include <cuda_runtime.h>
#include <cuda_fp16.h>

typedef unsigned int u32;

#define B_    16
#define C_    8
#define H_    512
#define W_    512
#define HW_   (H_*W_)
#define NPIX  (B_*HW_)
#define PGRID 592          // 4 CTAs x 148 SMs, all co-resident (grid-sync safe)
#define NTILE (B_*H_)      // 8192 row-tiles

__device__ u32 g_cnt;
__device__ u32 g_arr;
__device__ u32 g_dep;

__device__ __forceinline__ u32 pkh(float lo, float hi) {
    __half2 h = __floats2half2_rn(lo, hi);
    return *reinterpret_cast<u32*>(&h);
}
__device__ __forceinline__ u32 pkhr(float lo, float hi) {   // relu + pack
    __half2 h = __floats2half2_rn(fmaxf(lo, 0.0f), fmaxf(hi, 0.0f));
    return *reinterpret_cast<u32*>(&h);
}

// M=pixels, N=outputs: A = activations, B = weights (persistent regs)
__device__ __forceinline__ void mma16(float* d, u32 a0, u32 a1, u32 a2, u32 a3,
                                      u32 b0, u32 b1) {
    asm volatile(
        "mma.sync.aligned.m16n8k16.row.col.f32.f16.f16.f32 "
        "{%0,%1,%2,%3},{%4,%5,%6,%7},{%8,%9},{%0,%1,%2,%3};"
        : "+f"(d[0]), "+f"(d[1]), "+f"(d[2]), "+f"(d[3])
        : "r"(a0), "r"(a1), "r"(a2), "r"(a3), "r"(b0), "r"(b1));
}

__device__ __forceinline__ int swz(int px, int w) {
    return px * 20 + (w ^ ((px >> 3) & 15));
}

// raw row preload: vector + edge scalar (lane 0: left halo, lane 31: right halo)
__device__ __forceinline__ void prerow(const float* p, bool okRow, bool okL, bool okR,
                                       int lane, float4& v, float& e) {
    v = okRow ? __ldg(reinterpret_cast<const float4*>(p))
              : make_float4(0.f, 0.f, 0.f, 0.f);
    e = 0.0f;
    if (lane == 0  && okRow && okL) e = __ldg(p - 1);
    if (lane == 31 && okRow && okR) e = __ldg(p + 4);
}

// consume-time halo expansion via shuffles
__device__ __forceinline__ void expand(const float4& v, float e, int lane, float* n) {
    float l = __shfl_up_sync(0xffffffffu, v.w, 1);
    float r = __shfl_down_sync(0xffffffffu, v.x, 1);
    if (lane == 0)  l = e;
    if (lane == 31) r = e;
    n[0] = l; n[1] = v.x; n[2] = v.y; n[3] = v.z; n[4] = v.w; n[5] = r;
}

__global__ void __launch_bounds__(128, 4)
k_main(const float* __restrict__ x,
       const float* __restrict__ w1, const float* __restrict__ b1,
       const float* __restrict__ w2, const float* __restrict__ b2,
       const float* __restrict__ w3, const float* __restrict__ b3,
       const float* __restrict__ growth,
       float* __restrict__ out)
{
    __shared__ __align__(16) u32 sbuf[4 * 128 * 20];   // 40 KB
    __shared__ u32 s_part;
    __shared__ float s_bbase;

    const int tid  = threadIdx.x;
    const int wid  = tid >> 5;
    const int lane = tid & 31;
    const int q = lane >> 2;
    const int r = lane & 3;
    u32* bw = sbuf + wid * (128 * 20);

    // ================= Phase A: global alive count =================
    if (tid == 0) s_part = 0u;
    __syncthreads();
    {
        u32 cnt = 0;
        for (int b = 0; b < B_; b++) {
            const float4* p = reinterpret_cast<const float4*>(
                x + (size_t)b * (C_ * HW_) + (size_t)3 * HW_);
            for (int i = blockIdx.x * 128 + tid; i < HW_ / 4; i += PGRID * 128) {
                float4 v = __ldg(p + i);
                cnt += (v.x > 0.1f) + (v.y > 0.1f) + (v.z > 0.1f) + (v.w > 0.1f);
            }
        }
        #pragma unroll
        for (int o = 16; o; o >>= 1) cnt += __shfl_down_sync(0xffffffffu, cnt, o);
        if (lane == 0) atomicAdd(&s_part, cnt);
    }
    __syncthreads();
    if (tid == 0) {
        atomicAdd(&g_cnt, s_part);
        __threadfence();
        atomicAdd(&g_arr, 1u);
    }
    {
        volatile u32* va = &g_arr;
        while (*va < PGRID) __nanosleep(128);
    }
    __threadfence();
    if (tid == 0) {
        u32 total = *((volatile u32*)&g_cnt);
        s_bbase = ((float)total < 0.2f * (float)NPIX) ? 0.2f : 0.0f;
    }
    __syncthreads();
    const float bbase = s_bbase;
    if (tid == 0) {
        u32 d = atomicAdd(&g_dep, 1u);
        if (d == PGRID - 1) {
            g_cnt = 0u; g_arr = 0u; g_dep = 0u;
            __threadfence();
        }
    }

    // ================= persistent weight fragments =================
    u32 W1f[4][2][2];
    #pragma unroll
    for (int nt = 0; nt < 4; nt++)
        #pragma unroll
        for (int kt = 0; kt < 2; kt++) {
            const float* wr = w1 + (8 * nt + q) * 24;
            int k0 = 16 * kt + 2 * r;
            W1f[nt][kt][0] = pkh(__ldg(&wr[k0]), __ldg(&wr[k0 + 1]));
            W1f[nt][kt][1] = (kt == 0)
                ? pkh(__ldg(&wr[k0 + 8]), __ldg(&wr[k0 + 9])) : 0u;
        }
    u32 W2f[4][2][2];
    #pragma unroll
    for (int nt = 0; nt < 4; nt++)
        #pragma unroll
        for (int kt = 0; kt < 2; kt++) {
            const float* wr = w2 + (8 * nt + q) * 32;
            int k0 = 16 * kt + 2 * r;
            W2f[nt][kt][0] = pkh(__ldg(&wr[k0]), __ldg(&wr[k0 + 1]));
            W2f[nt][kt][1] = pkh(__ldg(&wr[k0 + 8]), __ldg(&wr[k0 + 9]));
        }
    u32 W3f[2][2];
    #pragma unroll
    for (int kt = 0; kt < 2; kt++) {
        const float* wr = w3 + q * 32;
        int k0 = 16 * kt + 2 * r;
        W3f[kt][0] = pkh(__ldg(&wr[k0]), __ldg(&wr[k0 + 1]));
        W3f[kt][1] = pkh(__ldg(&wr[k0 + 8]), __ldg(&wr[k0 + 9]));
    }
    float bA1[4], bB1[4], bA2[4], bB2[4];
    #pragma unroll
    for (int nt = 0; nt < 4; nt++) {
        bA1[nt] = __ldg(&b1[8 * nt + 2 * r]); bB1[nt] = __ldg(&b1[8 * nt + 2 * r + 1]);
        bA2[nt] = __ldg(&b2[8 * nt + 2 * r]); bB2[nt] = __ldg(&b2[8 * nt + 2 * r + 1]);
    }
    const float bA3 = __ldg(&b3[2 * r]), bB3 = __ldg(&b3[2 * r + 1]);
    const float gr  = __ldg(&growth[0]);
    const float AT  = 0.1f;

    // lane word-bases for strength-reduced fragment addressing
    u32 lbw[4];
    #pragma unroll
    for (int j = 0; j < 4; j++) lbw[j] = q * 20 + (r ^ j);

    // k-pad words 12..15 stay zero (fragment loads land in words [0,16) only)
    #pragma unroll
    for (int i = 0; i < 4; i++) {
        int px = 4 * lane + i;
        bw[swz(px, 12)] = 0u; bw[swz(px, 13)] = 0u;
        bw[swz(px, 14)] = 0u; bw[swz(px, 15)] = 0u;
    }

    // ================= Phase B: persistent tile loop =================
    for (int t = blockIdx.x; t < NTILE; t += PGRID) {
        const int yy = t & (H_ - 1);
        const int bz = t >> 9;
        const int x0 = wid * 128;
        const float* xb = x + (size_t)bz * (C_ * HW_);

        const bool okT = (yy > 0), okB = (yy < H_ - 1);
        const bool okL = (x0 > 0), okR = (x0 + 128 < W_);

        __syncwarp();   // prior tile fully consumed before overwriting pbuf

        // ---- perceive: 8 channels, 2-deep software pipeline on row loads ----
        u32 bm0 = 0, bm1 = 0, bm2 = 0, bm3 = 0;
        float m0v[4], sx0[4], sy0[4];          // even-channel results awaiting pairing

        float4 aT, aM, aB; float gT, gM, gB;   // stage 0 (channel s)
        float4 bT, bM, bB; float hT, hM, hB;   // stage 1 (channel s+1)
        {
            const float* b0 = xb + (size_t)yy * W_ + x0 + 4 * lane;       // ch 0
            prerow(b0 - W_, okT,  okL, okR, lane, aT, gT);
            prerow(b0,      true, okL, okR, lane, aM, gM);
            prerow(b0 + W_, okB,  okL, okR, lane, aB, gB);
            const float* b1p = b0 + HW_;                                   // ch 1
            prerow(b1p - W_, okT,  okL, okR, lane, bT, hT);
            prerow(b1p,      true, okL, okR, lane, bM, hM);
            prerow(b1p + W_, okB,  okL, okR, lane, bB, hB);
        }

        #pragma unroll
        for (int s = 0; s < 8; s++) {
            // issue channel s+2's loads BEFORE consuming channel s
            float4 cT, cM, cB; float iT = 0.f, iM = 0.f, iB = 0.f;
            if (s < 6) {
                const float* bn = xb + (size_t)(s + 2) * HW_
                                + (size_t)yy * W_ + x0 + 4 * lane;
                prerow(bn - W_, okT,  okL, okR, lane, cT, iT);
                prerow(bn,      true, okL, okR, lane, cM, iM);
                prerow(bn + W_, okB,  okL, okR, lane, cB, iB);
            } else {
                cT = cM = cB = make_float4(0.f, 0.f, 0.f, 0.f);
            }

            // consume channel s (stage 0)
            float nt_[6], nm_[6], nb_[6];
            expand(aT, gT, lane, nt_);
            expand(aM, gM, lane, nm_);
            expand(aB, gB, lane, nb_);

            float mv[4], sx[4], sy[4];
            #pragma unroll
            for (int i = 0; i < 4; i++) {
                mv[i] = nm_[i + 1];
                sx[i] = (nt_[i + 2] - nt_[i]) + 2.0f * (nm_[i + 2] - nm_[i])
                      + (nb_[i + 2] - nb_[i]);
                sy[i] = (nb_[i] + 2.0f * nb_[i + 1] + nb_[i + 2])
                      - (nt_[i] + 2.0f * nt_[i + 1] + nt_[i + 2]);
            }

            if (s == 3) {   // channel 3: 3x3 any-alive -> ballots
                bool a[6];
                #pragma unroll
                for (int j = 0; j < 6; j++)
                    a[j] = (nt_[j] > AT) | (nm_[j] > AT) | (nb_[j] > AT);
                bm0 = __ballot_sync(0xffffffffu, a[0] | a[1] | a[2]);
                bm1 = __ballot_sync(0xffffffffu, a[1] | a[2] | a[3]);
                bm2 = __ballot_sync(0xffffffffu, a[2] | a[3] | a[4]);
                bm3 = __ballot_sync(0xffffffffu, a[3] | a[4] | a[5]);
            }

            if ((s & 1) == 0) {
                #pragma unroll
                for (int i = 0; i < 4; i++) {
                    m0v[i] = mv[i]; sx0[i] = sx[i]; sy0[i] = sy[i];
                }
            } else {
                const int p = s >> 1;
                #pragma unroll
                for (int i = 0; i < 4; i++) {
                    int px = 4 * lane + i;
                    bw[swz(px, p)]     = pkh(m0v[i], mv[i]);
                    bw[swz(px, 4 + p)] = pkh(sx0[i], sx[i]);
                    bw[swz(px, 8 + p)] = pkh(sy0[i], sy[i]);
                }
            }

            // pipeline shift: stage1 -> stage0, new -> stage1
            aT = bT; aM = bM; aB = bB; gT = hT; gM = hM; gB = hB;
            bT = cT; bM = cM; bB = cB; hT = iT; hM = iM; hB = iB;
        }
        __syncwarp();

        // ---- L2 prefetch of NEXT tile's input rows (overlaps GEMM below) ----
        {
            int tn = t + PGRID;
            if (tn < NTILE) {
                int yyn = tn & (H_ - 1);
                int bzn = tn >> 9;
                const float* xbn = x + (size_t)bzn * (C_ * HW_);
                #pragma unroll
                for (int pl = 0; pl < 3; pl++) {
                    int l   = lane + 32 * pl;        // 0..95
                    int ch  = l / 12;
                    int rem = l - ch * 12;
                    int dy  = (rem >> 2) - 1;
                    int seg = rem & 3;
                    int yr  = yyn + dy;
                    if (yr >= 0 && yr < H_) {
                        const float* pa = xbn + (size_t)ch * HW_
                                        + (size_t)yr * W_ + x0 + seg * 32;
                        asm volatile("prefetch.global.L2 [%0];" :: "l"(pa));
                    }
                }
            }
        }

        // ---- 4 chunks of 32 px; layers chained in registers; dx staged fp16 ----
        #pragma unroll
        for (int cidx = 0; cidx < 4; cidx++) {
            const int P = 32 * cidx;

            float d1[2][4][4];
            #pragma unroll
            for (int mt = 0; mt < 2; mt++)
                #pragma unroll
                for (int nt = 0; nt < 4; nt++) {
                    d1[mt][nt][0] = bA1[nt]; d1[mt][nt][1] = bB1[nt];
                    d1[mt][nt][2] = bA1[nt]; d1[mt][nt][3] = bB1[nt];
                }
            #pragma unroll
            for (int kt = 0; kt < 2; kt++)
                #pragma unroll
                for (int mt = 0; mt < 2; mt++) {
                    const int m  = (4 * cidx + 2 * mt) & 15;
                    const int m1 = (m + 1) & 15;
                    const int C0 = (P + 16 * mt) * 20
                                 + ((8 * kt) ^ (m  & 8)) + (m  & 4);
                    const int C1 = (P + 16 * mt + 8) * 20
                                 + ((8 * kt) ^ (m1 & 8)) + (m1 & 4);
                    const int C2 = (P + 16 * mt) * 20
                                 + ((8 * kt) ^ (m  & 8)) + (4 ^ (m  & 4));
                    const int C3 = (P + 16 * mt + 8) * 20
                                 + ((8 * kt) ^ (m1 & 8)) + (4 ^ (m1 & 4));
                    u32 a0 = bw[lbw[m  & 3] + C0];
                    u32 a1 = bw[lbw[m1 & 3] + C1];
                    u32 a2 = bw[lbw[m  & 3] + C2];
                    u32 a3 = bw[lbw[m1 & 3] + C3];
                    #pragma unroll
                    for (int nt = 0; nt < 4; nt++)
                        mma16(d1[mt][nt], a0, a1, a2, a3, W1f[nt][kt][0], W1f[nt][kt][1]);
                }

            float d2[2][4][4];
            #pragma unroll
            for (int mt = 0; mt < 2; mt++)
                #pragma unroll
                for (int nt = 0; nt < 4; nt++) {
                    d2[mt][nt][0] = bA2[nt]; d2[mt][nt][1] = bB2[nt];
                    d2[mt][nt][2] = bA2[nt]; d2[mt][nt][3] = bB2[nt];
                }
            #pragma unroll
            for (int mt = 0; mt < 2; mt++)
                #pragma unroll
                for (int kt = 0; kt < 2; kt++) {
                    u32 a0 = pkhr(d1[mt][2 * kt][0],     d1[mt][2 * kt][1]);
                    u32 a1 = pkhr(d1[mt][2 * kt][2],     d1[mt][2 * kt][3]);
                    u32 a2 = pkhr(d1[mt][2 * kt + 1][0], d1[mt][2 * kt + 1][1]);
                    u32 a3 = pkhr(d1[mt][2 * kt + 1][2], d1[mt][2 * kt + 1][3]);
                    #pragma unroll
                    for (int nt = 0; nt < 4; nt++)
                        mma16(d2[mt][nt], a0, a1, a2, a3, W2f[nt][kt][0], W2f[nt][kt][1]);
                }

            float e[2][4];
            #pragma unroll
            for (int mt = 0; mt < 2; mt++) {
                e[mt][0] = bA3; e[mt][1] = bB3; e[mt][2] = bA3; e[mt][3] = bB3;
            }
            #pragma unroll
            for (int mt = 0; mt < 2; mt++)
                #pragma unroll
                for (int kt = 0; kt < 2; kt++) {
                    u32 a0 = pkhr(d2[mt][2 * kt][0],     d2[mt][2 * kt][1]);
                    u32 a1 = pkhr(d2[mt][2 * kt][2],     d2[mt][2 * kt][3]);
                    u32 a2 = pkhr(d2[mt][2 * kt + 1][0], d2[mt][2 * kt + 1][1]);
                    u32 a3 = pkhr(d2[mt][2 * kt + 1][2], d2[mt][2 * kt + 1][3]);
                    mma16(e[mt], a0, a1, a2, a3, W3f[kt][0], W3f[kt][1]);
                }

            // stage raw dx (pre-scale) as fp16 pairs into spare words 16..19
            #pragma unroll
            for (int mt = 0; mt < 2; mt++)
                #pragma unroll
                for (int h = 0; h < 2; h++) {
                    int px = P + 16 * mt + 8 * h + q;
                    int s  = ((px >> 2) ^ (2 * (px & 3))) | ((px & 3) << 5);
                    bw[s * 20 + 16 + r] = pkh(e[mt][2 * h], e[mt][2 * h + 1]);
                }
        }
        __syncwarp();   // dx staging visible across lanes

        // ---- vectorized epilogue: 4 px/lane, all 8 channels ----
        {
            const float* xrow = xb + (size_t)yy * W_ + x0 + 4 * lane;
            float* orow = out + (size_t)bz * (C_ * HW_) + (size_t)yy * W_ + x0 + 4 * lane;

            u32 dxw[4][4];
            #pragma unroll
            for (int i = 0; i < 4; i++) {
                int s = (lane ^ (2 * i)) | (i << 5);
                uint4 v = *reinterpret_cast<const uint4*>(&bw[s * 20 + 16]);
                dxw[i][0] = v.x; dxw[i][1] = v.y; dxw[i][2] = v.z; dxw[i][3] = v.w;
            }
            u32 bms[4] = {bm0, bm1, bm2, bm3};

            #pragma unroll
            for (int j = 0; j < 4; j++) {        // channel pair (2j, 2j+1)
                float4 xa = __ldg(reinterpret_cast<const float4*>(
                    xrow + (size_t)(2 * j) * HW_));
                float4 xc = __ldg(reinterpret_cast<const float4*>(
                    xrow + (size_t)(2 * j + 1) * HW_));
                float oa[4], oc[4];
                const float* xaf = &xa.x;
                const float* xcf = &xc.x;
                #pragma unroll
                for (int i = 0; i < 4; i++) {
                    __half2 hv = *reinterpret_cast<__half2*>(&dxw[i][j]);
                    float2 f = __half22float2(hv);
                    float dx0 = f.x * gr;
                    float dx1 = f.y * gr;
                    if (j == 1) {                // ch3 boost
                        if ((bms[i] >> lane) & 1u) dx1 += bbase;
                    }
                    float n0 = fminf(fmaxf(xaf[i] + dx0, -1.0f), 1.0f);
                    float n1 = fminf(fmaxf(xcf[i] + dx1, -1.0f), 1.0f);
                    if (j == 1) n1 = fmaxf(n1, 0.0f);   // alpha clamp
                    oa[i] = n0; oc[i] = n1;
                }
                *reinterpret_cast<float4*>(orow + (size_t)(2 * j) * HW_)
                    = make_float4(oa[0], oa[1], oa[2], oa[3]);
                *reinterpret_cast<float4*>(orow + (size_t)(2 * j + 1) * HW_)
                    = make_float4(oc[0], oc[1], oc[2], oc[3]);
            }
        }
    }
}

extern "C" void kernel_launch(void* const* d_in, const int* in_sizes, int n_in,
                              void* d_out, int out_size)
{
    const float* x  = (const float*)d_in[0];
    const float* w1 = (const float*)d_in[1];
    const float* b1 = (const float*)d_in[2];
    const float* w2 = (const float*)d_in[3];
    const float* b2 = (const float*)d_in[4];
    const float* w3 = (const float*)d_in[5];
    const float* b3 = (const float*)d_in[6];
    const float* gr = (const float*)d_in[7];
    float* out = (float*)d_out;

    k_main<<<PGRID, 128>>>(x, w1, b1, w2, b2, w3, b3, gr, out);
}